// round 15
// baseline (speedup 1.0000x reference)
#include <cuda_runtime.h>
#include <cuda_fp16.h>
#include <stdint.h>

#define D 128
#define NMAX 100000
#define EMAX 1600000
#define BN_EPS 1e-5f
#define NBANK 16
#define IDX_BITS 17
#define IDX_MASK 0x1FFFFu
#define CAP 128
#define XS_STRIDE 136

// ---------------- scratch (no allocations allowed) ----------------
__device__ __align__(16) __half g_XWh[(size_t)NMAX * D];        // 25.6 MB
__device__ __align__(16) unsigned g_bucket[(size_t)NMAX * CAP]; // 51.2 MB
__device__ __align__(16) __half g_Wt[D * D];                    // 32 KB W^T fp16 [n][k]
__device__ int   g_deg[NMAX];
__device__ float g_sumP[NBANK][D];
__device__ float g_sumsqP[NBANK][D];
__device__ int   g_ei64;
__device__ int   g_et64;

// ---------------- safe bit-cast helpers ----------------
__device__ __forceinline__ __half2 u32_to_h2(unsigned u) {
    __half2 h; memcpy(&h, &u, 4); return h;
}

// ---------------- prologue ----------------
__global__ void prologue_kernel(const int* ei_as_i32, const int* et_as_i32,
                                const float* __restrict__ W) {
    int t = threadIdx.x;
    for (int k = t; k < NBANK * D; k += 256) {
        ((float*)g_sumP)[k] = 0.0f;
        ((float*)g_sumsqP)[k] = 0.0f;
    }
    for (int i = t; i < D * D; i += 256) {
        int n = i >> 7, k = i & 127;
        g_Wt[n * D + k] = __float2half(W[k * D + n]);
    }
    if (t == 0) {
        int allz = 1;
        #pragma unroll
        for (int k = 0; k < 16; k++) if (ei_as_i32[2 * k + 1] != 0) allz = 0;
        g_ei64 = allz;
        allz = 1;
        #pragma unroll
        for (int k = 0; k < 16; k++) if (et_as_i32[2 * k + 1] != 0) allz = 0;
        g_et64 = allz;
    }
}

// ---------------- mma helper ----------------
__device__ __forceinline__ void mma_16x8x16(
    float& c0, float& c1, float& c2, float& c3,
    unsigned a0, unsigned a1, unsigned a2, unsigned a3,
    unsigned b0, unsigned b1)
{
    asm("mma.sync.aligned.m16n8k16.row.col.f32.f16.f16.f32 "
        "{%0,%1,%2,%3}, {%4,%5,%6,%7}, {%8,%9}, {%0,%1,%2,%3};"
        : "+f"(c0), "+f"(c1), "+f"(c2), "+f"(c3)
        : "r"(a0), "r"(a1), "r"(a2), "r"(a3), "r"(b0), "r"(b1));
}

// ---------------- fused: tensor-core GEMM + fill + r copy ----------------
__global__ __launch_bounds__(256) void gemm_fill_kernel(
    const float* __restrict__ x,
    const void* __restrict__ ei_raw, const void* __restrict__ et_raw,
    const float* __restrict__ r_in, float* __restrict__ r_out,
    int N, long E, long r_count, int GB, int HB)
{
    const int b = (int)blockIdx.x;
    if (b < GB) {
        __shared__ __half Xs[64][XS_STRIDE];
        const int tid = threadIdx.x;
        const int r0b = b * 64;

        for (int idx = tid; idx < 64 * 32; idx += 256) {
            int r = idx >> 5, q = idx & 31;
            float4 v = make_float4(0.f, 0.f, 0.f, 0.f);
            if (r0b + r < N) v = *(const float4*)&x[(size_t)(r0b + r) * D + q * 4];
            __half2* dst = (__half2*)&Xs[r][q * 4];
            dst[0] = __floats2half2_rn(v.x, v.y);
            dst[1] = __floats2half2_rn(v.z, v.w);
        }
        __syncthreads();

        const int w = tid >> 5;
        const int lane = tid & 31;
        const int rw = (w & 3) * 16;
        const int nhalf = (w >> 2) * 64;
        const int g  = lane >> 2;
        const int tg = lane & 3;

        float c[8][4];
        #pragma unroll
        for (int nt = 0; nt < 8; nt++)
            #pragma unroll
            for (int j = 0; j < 4; j++) c[nt][j] = 0.0f;

        #pragma unroll
        for (int kk = 0; kk < 8; kk++) {
            const int k0 = kk * 16;
            unsigned a0 = *(const unsigned*)&Xs[rw + g][k0 + tg * 2];
            unsigned a1 = *(const unsigned*)&Xs[rw + g + 8][k0 + tg * 2];
            unsigned a2 = *(const unsigned*)&Xs[rw + g][k0 + tg * 2 + 8];
            unsigned a3 = *(const unsigned*)&Xs[rw + g + 8][k0 + tg * 2 + 8];
            #pragma unroll
            for (int nt = 0; nt < 8; nt++) {
                int n = nhalf + nt * 8 + g;
                unsigned b0 = __ldg((const unsigned*)&g_Wt[n * D + k0 + tg * 2]);
                unsigned b1 = __ldg((const unsigned*)&g_Wt[n * D + k0 + tg * 2 + 8]);
                mma_16x8x16(c[nt][0], c[nt][1], c[nt][2], c[nt][3],
                            a0, a1, a2, a3, b0, b1);
            }
        }

        const int r1 = r0b + rw + g;
        const int r2 = r1 + 8;
        #pragma unroll
        for (int nt = 0; nt < 8; nt++) {
            int cb = nhalf + nt * 8 + tg * 2;
            if (r1 < N)
                *(__half2*)&g_XWh[(size_t)r1 * D + cb] = __floats2half2_rn(c[nt][0], c[nt][1]);
            if (r2 < N)
                *(__half2*)&g_XWh[(size_t)r2 * D + cb] = __floats2half2_rn(c[nt][2], c[nt][3]);
        }
    } else if (b < GB + HB) {
        long e = (long)(b - GB) * 256 + threadIdx.x;
        if (e >= E) return;
        int row, col, et;
        if (g_ei64) {
            const long long* p = (const long long*)ei_raw;
            row = (int)p[e]; col = (int)p[E + e];
        } else {
            const int* p = (const int*)ei_raw;
            row = p[e]; col = p[E + e];
        }
        if (g_et64) et = (int)((const long long*)et_raw)[e];
        else        et = ((const int*)et_raw)[e];
        unsigned pk_col = (unsigned)col | ((unsigned)et << IDX_BITS);
        unsigned pk_row = (unsigned)row | ((unsigned)et << IDX_BITS);
        int s1 = atomicAdd(&g_deg[row], 1);
        if (s1 < CAP) g_bucket[(size_t)row * CAP + s1] = pk_col;
        int s2 = atomicAdd(&g_deg[col], 1);
        if (s2 < CAP) g_bucket[(size_t)col * CAP + s2] = pk_row;
    } else {
        const int nb = gridDim.x - GB - HB;
        long rc4 = r_count >> 2;
        long stride = (long)nb * 256;
        for (long i4 = (long)(b - GB - HB) * 256 + threadIdx.x; i4 < rc4; i4 += stride) {
            ((float4*)r_out)[i4] = ((const float4*)r_in)[i4];
        }
        if (b == GB + HB && threadIdx.x == 0) {
            for (long i = rc4 << 2; i < r_count; i++) r_out[i] = r_in[i];
        }
    }
}

// ---------------- gather: warp per node, packed f32x2 accumulate ----------------
// acc kept as two f32x2 pairs; fma.rn.f32x2 halves FMA-pipe instruction count.
__device__ __forceinline__ void acc_f32x2(
    unsigned long long& acc01, unsigned long long& acc23, float a, uint2 u)
{
    float2 lo = __half22float2(u32_to_h2(u.x));
    float2 hi = __half22float2(u32_to_h2(u.y));
    unsigned long long v01, v23, aa;
    asm("mov.b64 %0, {%1,%2};" : "=l"(v01) : "f"(lo.x), "f"(lo.y));
    asm("mov.b64 %0, {%1,%2};" : "=l"(v23) : "f"(hi.x), "f"(hi.y));
    asm("mov.b64 %0, {%1,%1};" : "=l"(aa)  : "f"(a));
    asm("fma.rn.f32x2 %0, %1, %2, %0;" : "+l"(acc01) : "l"(v01), "l"(aa));
    asm("fma.rn.f32x2 %0, %1, %2, %0;" : "+l"(acc23) : "l"(v23), "l"(aa));
}

__global__ __launch_bounds__(256) void gather_kernel(
    const float* __restrict__ alpha, const float* __restrict__ bias,
    float* __restrict__ out, int N, int selfRel)
{
    const int lane = threadIdx.x & 31;
    const int warpG = (blockIdx.x * blockDim.x + threadIdx.x) >> 5;
    const int nWarps = (gridDim.x * blockDim.x) >> 5;
    const uint2* XH = (const uint2*)g_XWh;

    const float a2 = 2.0f * __ldg(alpha + selfRel);
    const float4 b4 = __ldg((const float4*)bias + lane);

    float s0 = 0, s1 = 0, s2 = 0, s3 = 0;
    float q0 = 0, q1 = 0, q2 = 0, q3 = 0;

    for (int i = warpG; i < N; i += nWarps) {
        int deg = g_deg[i];
        if (deg > CAP) deg = CAP;
        const unsigned* bkt = g_bucket + (size_t)i * CAP;

        unsigned long long acc01, acc23;
        asm("mov.b64 %0, {%1,%2};" : "=l"(acc01) : "f"(b4.x), "f"(b4.y));
        asm("mov.b64 %0, {%1,%2};" : "=l"(acc23) : "f"(b4.z), "f"(b4.w));
        acc_f32x2(acc01, acc23, a2, XH[(size_t)i * 32 + lane]);

        for (int base = 0; base < deg; base += 32) {
            int cnt = deg - base;
            if (cnt > 32) cnt = 32;
            unsigned meta = 0;
            float aL = 0.0f;
            if (lane < cnt) {
                meta = bkt[base + lane];
                aL = __ldg(alpha + (meta >> IDX_BITS));
            }
            int g = 0;
            for (; g + 4 <= cnt; g += 4) {
                unsigned m0 = __shfl_sync(0xFFFFFFFFu, meta, g + 0);
                unsigned m1 = __shfl_sync(0xFFFFFFFFu, meta, g + 1);
                unsigned m2 = __shfl_sync(0xFFFFFFFFu, meta, g + 2);
                unsigned m3 = __shfl_sync(0xFFFFFFFFu, meta, g + 3);
                float a0 = __shfl_sync(0xFFFFFFFFu, aL, g + 0);
                float a1 = __shfl_sync(0xFFFFFFFFu, aL, g + 1);
                float c2 = __shfl_sync(0xFFFFFFFFu, aL, g + 2);
                float c3 = __shfl_sync(0xFFFFFFFFu, aL, g + 3);
                uint2 v0 = XH[(size_t)(m0 & IDX_MASK) * 32 + lane];
                uint2 v1 = XH[(size_t)(m1 & IDX_MASK) * 32 + lane];
                uint2 v2 = XH[(size_t)(m2 & IDX_MASK) * 32 + lane];
                uint2 v3 = XH[(size_t)(m3 & IDX_MASK) * 32 + lane];
                acc_f32x2(acc01, acc23, a0, v0);
                acc_f32x2(acc01, acc23, a1, v1);
                acc_f32x2(acc01, acc23, c2, v2);
                acc_f32x2(acc01, acc23, c3, v3);
            }
            for (; g < cnt; g++) {
                unsigned m0 = __shfl_sync(0xFFFFFFFFu, meta, g);
                float a0 = __shfl_sync(0xFFFFFFFFu, aL, g);
                acc_f32x2(acc01, acc23, a0, XH[(size_t)(m0 & IDX_MASK) * 32 + lane]);
            }
        }

        float4 acc;
        asm("mov.b64 {%0,%1}, %2;" : "=f"(acc.x), "=f"(acc.y) : "l"(acc01));
        asm("mov.b64 {%0,%1}, %2;" : "=f"(acc.z), "=f"(acc.w) : "l"(acc23));

        ((float4*)out)[(size_t)i * 32 + lane] = acc;
        s0 += acc.x; s1 += acc.y; s2 += acc.z; s3 += acc.w;
        q0 += acc.x * acc.x; q1 += acc.y * acc.y;
        q2 += acc.z * acc.z; q3 += acc.w * acc.w;
    }

    __shared__ float ssum[D], ssq[D];
    int t = threadIdx.x;
    if (t < D) { ssum[t] = 0.0f; ssq[t] = 0.0f; }
    __syncthreads();
    int c = lane * 4;
    atomicAdd(&ssum[c + 0], s0); atomicAdd(&ssum[c + 1], s1);
    atomicAdd(&ssum[c + 2], s2); atomicAdd(&ssum[c + 3], s3);
    atomicAdd(&ssq[c + 0], q0);  atomicAdd(&ssq[c + 1], q1);
    atomicAdd(&ssq[c + 2], q2);  atomicAdd(&ssq[c + 3], q3);
    __syncthreads();
    if (t < D) {
        int bank = blockIdx.x & (NBANK - 1);
        atomicAdd(&g_sumP[bank][t], ssum[t]);
        atomicAdd(&g_sumsqP[bank][t], ssq[t]);
    }
}

// ---------------- normalize (float4) + re-zero g_deg ----------------
__global__ __launch_bounds__(256) void norm_kernel(
    float* __restrict__ out, const float* __restrict__ gamma,
    const float* __restrict__ beta, int N)
{
    __shared__ float sc[D], sh[D];
    const int t = threadIdx.x;
    if (t < D) {
        float s = 0.0f, q = 0.0f;
        #pragma unroll
        for (int b = 0; b < NBANK; b++) { s += g_sumP[b][t]; q += g_sumsqP[b][t]; }
        float invN = 1.0f / (float)N;
        float mean = s * invN;
        float var = q * invN - mean * mean;
        float scl = gamma[t] * rsqrtf(var + BN_EPS);
        sc[t] = scl;
        sh[t] = beta[t] - mean * scl;
    }
    __syncthreads();

    float4* out4 = (float4*)out;
    const float4* sc4 = (const float4*)sc;
    const float4* sh4 = (const float4*)sh;

    size_t total4 = (size_t)N * 32;
    size_t stride = (size_t)gridDim.x * blockDim.x;
    size_t start = (size_t)blockIdx.x * blockDim.x + t;
    for (size_t idx = start; idx < total4; idx += stride) {
        int c4 = (int)(idx & 31);
        float4 v = out4[idx];
        float4 s = sc4[c4];
        float4 h = sh4[c4];
        v.x = v.x * s.x + h.x;
        v.y = v.y * s.y + h.y;
        v.z = v.z * s.z + h.z;
        v.w = v.w * s.w + h.w;
        out4[idx] = v;
    }
    int4* deg4 = (int4*)g_deg;
    size_t n4 = (size_t)(N >> 2);
    for (size_t idx = start; idx < n4; idx += stride) {
        deg4[idx] = make_int4(0, 0, 0, 0);
    }
    if (start == 0) {
        for (int i = (int)(n4 * 4); i < N; i++) g_deg[i] = 0;
    }
}

// ---------------- launch ----------------
extern "C" void kernel_launch(void* const* d_in, const int* in_sizes, int n_in,
                              void* d_out, int out_size)
{
    const float* x     = (const float*)d_in[0];
    const float* r     = (const float*)d_in[1];
    const void*  ei    = d_in[2];
    const void*  etype = d_in[3];
    const float* W     = (const float*)d_in[4];
    const float* alpha = (const float*)d_in[5];
    const float* bias  = (const float*)d_in[6];
    const float* gamma = (const float*)d_in[7];
    const float* beta  = (const float*)d_in[8];
    float* out = (float*)d_out;

    const int  N       = in_sizes[0] / D;       // 100000
    const long E       = (long)in_sizes[3];     // 1600000
    const int  numRel  = in_sizes[1] / D;       // 1001
    const int  selfRel = numRel - 1;            // 1000
    const long r_count = (long)in_sizes[1];

    float* r_out = out + (size_t)N * D;
    const int GB = (N + 63) / 64;                       // 1563
    const int HB = (int)((E + 255) / 256);              // 6250
    const int RB = (int)(((r_count >> 2) + 255) / 256); // ~126

    prologue_kernel<<<1, 256>>>((const int*)ei, (const int*)etype, W);

    gemm_fill_kernel<<<GB + HB + RB, 256>>>(x, ei, etype, r, r_out,
                                            N, E, r_count, GB, HB);

    gather_kernel<<<2048, 256>>>(alpha, bias, out, N, selfRel);

    norm_kernel<<<2048, 256>>>(out, gamma, beta, N);
}